// round 1
// baseline (speedup 1.0000x reference)
#include <cuda_runtime.h>
#include <math.h>

#define Bn 4
#define Tn 8
#define Hn 256
#define Wn 256
#define NPIX (Bn*Tn*Hn*Wn)   // 2,097,152 elements per field

// Scratch (static device globals -- no allocation allowed)
__device__ float g_fields[8][NPIX];  // 0:kappa^2 1:m1 2:m2 3:Hxx 4:Hxy 5:Hyx 6:Hyy 7:D
__device__ float g_v[NPIX];          // v = A(x)
__device__ double g_acc[2];          // [0] = sum(D r^2), [1] = sum(log D)

__global__ void init_acc_kernel() {
    g_acc[0] = 0.0;
    g_acc[1] = 0.0;
}

// ---------------------------------------------------------------------------
// Kernel 1: 3x3 conv (8 -> 64 channels) + per-group nonlinearity + field store
// Tile: 32 wide x 8 tall pixels. 256 threads. warp id (tn) = output group g.
// Each thread: 8 pixel-rows (fixed column tm) x 8 t-channels accumulators.
// ---------------------------------------------------------------------------
#define TW 32
#define TH 8

__global__ __launch_bounds__(256) void conv_kernel(const float* __restrict__ x,
                                                   const float* __restrict__ cw)
{
    __shared__ float xs[8][TH + 2][TW + 2];        // 8 ch x 10 x 34
    __shared__ __align__(16) float ws[72 * 64];    // [k][o], o fastest

    const int tid = threadIdx.x;
    const int b  = blockIdx.z;
    const int h0 = blockIdx.y * TH;
    const int w0 = blockIdx.x * TW;

    // weights transposed: ws[k*64 + o] = cw[o*72 + k]   (L2-resident, 18KB)
    for (int i = tid; i < 72 * 64; i += 256) {
        int k = i >> 6, o = i & 63;
        ws[i] = cw[o * 72 + k];
    }
    // x tile with halo 1 (zero Dirichlet)
    for (int i = tid; i < 8 * (TH + 2) * (TW + 2); i += 256) {
        int ci  = i / ((TH + 2) * (TW + 2));
        int rem = i % ((TH + 2) * (TW + 2));
        int yy  = rem / (TW + 2);
        int xx  = rem % (TW + 2);
        int gy = h0 - 1 + yy, gx = w0 - 1 + xx;
        float v = 0.f;
        if (gy >= 0 && gy < Hn && gx >= 0 && gx < Wn)
            v = x[(((b * Tn) + ci) * Hn + gy) * Wn + gx];
        xs[ci][yy][xx] = v;
    }
    __syncthreads();

    const int tn = tid >> 5;   // warp = group g (0..7)
    const int tm = tid & 31;   // pixel column within tile

    float acc[8][8];
    #pragma unroll
    for (int i = 0; i < 8; i++)
        #pragma unroll
        for (int j = 0; j < 8; j++) acc[i][j] = 0.f;

    const int obase = tn * 8;
    for (int ci = 0; ci < 8; ci++) {
        #pragma unroll
        for (int ky = 0; ky < 3; ky++) {
            #pragma unroll
            for (int kx = 0; kx < 3; kx++) {
                const int k = ci * 9 + ky * 3 + kx;
                float4 wv0 = *(const float4*)&ws[k * 64 + obase];
                float4 wv1 = *(const float4*)&ws[k * 64 + obase + 4];
                #pragma unroll
                for (int i = 0; i < 8; i++) {
                    float xv = xs[ci][i + ky][tm + kx];
                    acc[i][0] += xv * wv0.x;
                    acc[i][1] += xv * wv0.y;
                    acc[i][2] += xv * wv0.z;
                    acc[i][3] += xv * wv0.w;
                    acc[i][4] += xv * wv1.x;
                    acc[i][5] += xv * wv1.y;
                    acc[i][6] += xv * wv1.z;
                    acc[i][7] += xv * wv1.w;
                }
            }
        }
    }

    // Nonlinearity (warp-uniform branch on tn) + coalesced field stores
    float lsum = 0.f;
    #pragma unroll
    for (int i = 0; i < 8; i++) {
        const int h = h0 + i;
        #pragma unroll
        for (int j = 0; j < 8; j++) {
            float a = acc[i][j];
            float r;
            if (tn == 0) {                       // kappa -> store kappa^2
                float s = 1.f / (1.f + expf(-a));
                float kp = s * 0.99f + 0.01f;
                r = kp * kp;
            } else if (tn == 1 || tn == 2) {     // m1, m2 raw
                r = a;
            } else if (tn == 3 || tn == 6) {     // Hxx, Hyy
                float s = 1.f / (1.f + expf(-a));
                r = s * 0.99f + 0.01f;
            } else if (tn == 4 || tn == 5) {     // Hxy, Hyx
                r = 0.1f * tanhf(a);
            } else {                              // tau -> store D = 1/tau^2
                float s = 1.f / (1.f + expf(-a));
                float tau = s * 9.9f + 0.1f;
                r = 1.f / (tau * tau);
                lsum += logf(r);
            }
            g_fields[tn][(((b * Tn) + j) * Hn + h) * Wn + w0 + tm] = r;
        }
    }

    if (tn == 7) {   // accumulate logdet(D)
        #pragma unroll
        for (int off = 16; off; off >>= 1)
            lsum += __shfl_down_sync(0xffffffffu, lsum, off);
        if (tm == 0) atomicAdd(&g_acc[1], (double)lsum);
    }
}

// ---------------------------------------------------------------------------
// Stencil operator A(u) at (b,t,h,w), zero Dirichlet boundaries.
// ---------------------------------------------------------------------------
__device__ __forceinline__ float applyA(const float* __restrict__ u,
                                        int base, int h, int w)
{
    float c   = u[base + h * Wn + w];
    float xr  = (w + 1 < Wn) ? u[base + h * Wn + w + 1] : 0.f;
    float xl  = (w - 1 >= 0) ? u[base + h * Wn + w - 1] : 0.f;
    float xd  = (h + 1 < Hn) ? u[base + (h + 1) * Wn + w] : 0.f;
    float xu  = (h - 1 >= 0) ? u[base + (h - 1) * Wn + w] : 0.f;
    float xdr = (h + 1 < Hn && w + 1 < Wn) ? u[base + (h + 1) * Wn + w + 1] : 0.f;
    float xdl = (h + 1 < Hn && w - 1 >= 0) ? u[base + (h + 1) * Wn + w - 1] : 0.f;
    float xur = (h - 1 >= 0 && w + 1 < Wn) ? u[base + (h - 1) * Wn + w + 1] : 0.f;
    float xul = (h - 1 >= 0 && w - 1 >= 0) ? u[base + (h - 1) * Wn + w - 1] : 0.f;

    const int p = base + h * Wn + w;
    float dx  = 0.5f * (xr - xl);
    float dy  = 0.5f * (xd - xu);
    float dxx = xr + xl - 2.f * c;
    float dyy = xd + xu - 2.f * c;
    float dxy = 0.25f * ((xdr - xur) - (xdl - xul));

    return g_fields[0][p] * c
         + g_fields[1][p] * dx
         + g_fields[2][p] * dy
         - (g_fields[3][p] * dxx
          + g_fields[6][p] * dyy
          + (g_fields[4][p] + g_fields[5][p]) * dxy);
}

// Kernel 2: v = A(x)
__global__ __launch_bounds__(Wn) void stencil1_kernel(const float* __restrict__ x)
{
    const int w = threadIdx.x;
    const int h = blockIdx.x;
    const int t = blockIdx.y;
    const int b = blockIdx.z;
    const int base = ((b * Tn + t) * Hn) * Wn;
    g_v[base + h * Wn + w] = applyA(x, base, h, w);
}

// Kernel 3: r = x + A(v) - x_prev ; accumulate sum(D r^2)
__global__ __launch_bounds__(Wn) void stencil2_kernel(const float* __restrict__ x)
{
    const int w = threadIdx.x;
    const int h = blockIdx.x;
    const int t = blockIdx.y;
    const int b = blockIdx.z;
    const int base = ((b * Tn + t) * Hn) * Wn;
    const int p = base + h * Wn + w;

    float Av    = applyA(g_v, base, h, w);
    float Mx    = x[p] + Av;                           // dt = 1
    float xprev = (t > 0) ? x[p - Hn * Wn] : 0.f;
    float r     = Mx - xprev;
    float val   = g_fields[7][p] * r * r;

    // block reduction (256 threads)
    #pragma unroll
    for (int off = 16; off; off >>= 1)
        val += __shfl_down_sync(0xffffffffu, val, off);

    __shared__ float red[8];
    const int lane = threadIdx.x & 31;
    const int wid  = threadIdx.x >> 5;
    if (lane == 0) red[wid] = val;
    __syncthreads();
    if (wid == 0) {
        float s = (lane < 8) ? red[lane] : 0.f;
        #pragma unroll
        for (int off = 4; off; off >>= 1)
            s += __shfl_down_sync(0xffffffffu, s, off);
        if (lane == 0) atomicAdd(&g_acc[0], (double)s);
    }
}

__global__ void finalize_kernel(float* __restrict__ out)
{
    out[0] = (float)(0.5 * (g_acc[0] - g_acc[1]));
}

// ---------------------------------------------------------------------------
extern "C" void kernel_launch(void* const* d_in, const int* in_sizes, int n_in,
                              void* d_out, int out_size)
{
    const float* x  = (const float*)d_in[0];
    const float* cw = (const float*)d_in[1];
    float* out = (float*)d_out;

    init_acc_kernel<<<1, 1>>>();

    dim3 gA(Wn / TW, Hn / TH, Bn);       // 8 x 32 x 4 = 1024 blocks
    conv_kernel<<<gA, 256>>>(x, cw);

    dim3 gS(Hn, Tn, Bn);                 // 256 x 8 x 4 blocks, 256 threads
    stencil1_kernel<<<gS, Wn>>>(x);
    stencil2_kernel<<<gS, Wn>>>(x);

    finalize_kernel<<<1, 1>>>(out);
}